// round 9
// baseline (speedup 1.0000x reference)
#include <cuda_runtime.h>
#include <cuda_fp16.h>
#include <cstdint>

#define NUM_EMB 41025
#define BATCH   16384
#define BAG     30
#define P       8          // positions per block
#define NT      256
#define GRID    (BATCH / P)

#define ROW_U4  32                     // 256 halves = 32 uint4 per row
#define TBL_U4  (NUM_EMB * ROW_U4)     // 1,312,800 uint4 per table

// fp16 shadow tables (scratch): [0]=white, [1]=black. 21 MB each.
__device__ uint4 g_ft16[2][TBL_U4];

// ---- packed f32x2 helpers (Blackwell sm_103a) ----
__device__ __forceinline__ void add_f32x2(uint64_t& acc, uint64_t v) {
    asm("add.rn.f32x2 %0, %1, %2;" : "=l"(acc) : "l"(acc), "l"(v));
}
__device__ __forceinline__ void fma_f32x2(uint64_t& acc, uint64_t a, uint64_t b) {
    asm("fma.rn.f32x2 %0, %1, %2, %3;" : "=l"(acc) : "l"(a), "l"(b), "l"(acc));
}
__device__ __forceinline__ uint64_t h2_to_f32x2(__half2 h) {
    float2 f = __half22float2(h);
    uint64_t r;
    asm("mov.b64 %0, {%1, %2};" : "=l"(r) : "f"(f.x), "f"(f.y));
    return r;
}
__device__ __forceinline__ float2 unpack_f32x2(uint64_t v) {
    float2 f;
    asm("mov.b64 {%0, %1}, %2;" : "=f"(f.x), "=f"(f.y) : "l"(v));
    return f;
}
__device__ __forceinline__ uint64_t pack_f32x2(float x, float y) {
    uint64_t r;
    asm("mov.b64 %0, {%1, %2};" : "=l"(r) : "f"(x), "f"(y));
    return r;
}

// ---------------------------------------------------------------------------
// Pre-pass: convert both f32 tables to fp16.
// ---------------------------------------------------------------------------
__global__ __launch_bounds__(256)
void cvt_kernel(const float4* __restrict__ ftw, const float4* __restrict__ ftb)
{
    const int i = blockIdx.x * blockDim.x + threadIdx.x;
    if (i >= 2 * TBL_U4) return;
    const int tbl = (i >= TBL_U4);
    const int j   = tbl ? (i - TBL_U4) : i;
    const float4* src = tbl ? ftb : ftw;

    const float4 a = __ldg(&src[2 * j]);
    const float4 b = __ldg(&src[2 * j + 1]);

    __half2 h0 = __floats2half2_rn(a.x, a.y);
    __half2 h1 = __floats2half2_rn(a.z, a.w);
    __half2 h2 = __floats2half2_rn(b.x, b.y);
    __half2 h3 = __floats2half2_rn(b.z, b.w);

    uint4 o;
    o.x = *reinterpret_cast<unsigned*>(&h0);
    o.y = *reinterpret_cast<unsigned*>(&h1);
    o.z = *reinterpret_cast<unsigned*>(&h2);
    o.w = *reinterpret_cast<unsigned*>(&h3);
    g_ft16[tbl][j] = o;
}

// ---------------------------------------------------------------------------
// Main kernel. 3 CTAs/SM target: FC1 done in 2 phases of 2 outputs/warp so
// only 32 weight registers are live at a time.
// ---------------------------------------------------------------------------
__global__ __launch_bounds__(NT, 3)
void nnue_kernel(const int* __restrict__ wi,
                 const int* __restrict__ bi,
                 const float4* __restrict__ fc1w,   // [32][128] float4
                 const float* __restrict__ fc1b,
                 const float4* __restrict__ fc2w,   // [32][8] float4
                 const float* __restrict__ fc2b,
                 const float* __restrict__ fc3w,
                 const float* __restrict__ fc3b,
                 float* __restrict__ out)
{
    __shared__ int    s_idx[P][2][BAG];
    __shared__ float4 s_x[P][128];     // concat(white,black) after relu
    __shared__ float  s_h1[P][32];

    const int tid  = threadIdx.x;
    const int lane = tid & 31;
    const int warp = tid >> 5;
    const int p0   = blockIdx.x * P;

    // ---- stage indices ----
    for (int i = tid; i < P * 2 * BAG; i += NT) {
        const int pp  = i / (2 * BAG);
        const int r   = i % (2 * BAG);
        const int tbl = r / BAG;
        const int j   = r % BAG;
        s_idx[pp][tbl][j] = tbl ? bi[(p0 + pp) * BAG + j]
                                : wi[(p0 + pp) * BAG + j];
    }
    __syncthreads();

    // ---- gather: warp w owns position w. fp16 rows, chunk-of-3 HADD2
    //      accumulation, merged into packed f32x2 accumulators. ----
    {
        uint64_t accW[4], accB[4];         // f32x2 accumulators (8 cols)
#pragma unroll
        for (int k = 0; k < 4; k++) { accW[k] = 0ull; accB[k] = 0ull; }

        const uint4* tw = g_ft16[0];
        const uint4* tb = g_ft16[1];
        const int* iw_p = s_idx[warp][0];
        const int* ib_p = s_idx[warp][1];

#pragma unroll 2
        for (int c = 0; c < 10; c++) {     // 10 chunks x 3 rows
            __half2 hsW[4], hsB[4];
            {
                const int iw = iw_p[3 * c];
                const int ib = ib_p[3 * c];
                const uint4 vw = __ldg(&tw[(size_t)iw * ROW_U4 + lane]);
                const uint4 vb = __ldg(&tb[(size_t)ib * ROW_U4 + lane]);
                const __half2* hw = reinterpret_cast<const __half2*>(&vw);
                const __half2* hb = reinterpret_cast<const __half2*>(&vb);
#pragma unroll
                for (int k = 0; k < 4; k++) { hsW[k] = hw[k]; hsB[k] = hb[k]; }
            }
#pragma unroll
            for (int jj = 1; jj < 3; jj++) {
                const int iw = iw_p[3 * c + jj];
                const int ib = ib_p[3 * c + jj];
                const uint4 vw = __ldg(&tw[(size_t)iw * ROW_U4 + lane]);
                const uint4 vb = __ldg(&tb[(size_t)ib * ROW_U4 + lane]);
                const __half2* hw = reinterpret_cast<const __half2*>(&vw);
                const __half2* hb = reinterpret_cast<const __half2*>(&vb);
#pragma unroll
                for (int k = 0; k < 4; k++) {
                    hsW[k] = __hadd2(hsW[k], hw[k]);
                    hsB[k] = __hadd2(hsB[k], hb[k]);
                }
            }
#pragma unroll
            for (int k = 0; k < 4; k++) {
                add_f32x2(accW[k], h2_to_f32x2(hsW[k]));
                add_f32x2(accB[k], h2_to_f32x2(hsB[k]));
            }
        }

        // relu + store to smem. lane holds cols 8*lane..8*lane+7.
        float aw[8], ab[8];
#pragma unroll
        for (int k = 0; k < 4; k++) {
            const float2 fw = unpack_f32x2(accW[k]);
            const float2 fb = unpack_f32x2(accB[k]);
            aw[2 * k]     = fmaxf(fw.x, 0.f);
            aw[2 * k + 1] = fmaxf(fw.y, 0.f);
            ab[2 * k]     = fmaxf(fb.x, 0.f);
            ab[2 * k + 1] = fmaxf(fb.y, 0.f);
        }
        s_x[warp][2 * lane]          = make_float4(aw[0], aw[1], aw[2], aw[3]);
        s_x[warp][2 * lane + 1]      = make_float4(aw[4], aw[5], aw[6], aw[7]);
        s_x[warp][64 + 2 * lane]     = make_float4(ab[0], ab[1], ab[2], ab[3]);
        s_x[warp][64 + 2 * lane + 1] = make_float4(ab[4], ab[5], ab[6], ab[7]);
    }
    __syncthreads();

    // ---- FC1 in 2 phases: warp computes outputs 4*warp+2*ph+{0,1} for all
    //      8 positions. Only 16 weight f32x2 regs live at a time. ----
#pragma unroll
    for (int ph = 0; ph < 2; ph++) {
        uint64_t wp[2][8];
        float    b1r[2];
#pragma unroll
        for (int oo = 0; oo < 2; oo++) {
            const int o = 4 * warp + 2 * ph + oo;
#pragma unroll
            for (int k = 0; k < 4; k++) {
                const float4 w = __ldg(&fc1w[(size_t)o * 128 + lane + 32 * k]);
                wp[oo][2 * k]     = pack_f32x2(w.x, w.y);
                wp[oo][2 * k + 1] = pack_f32x2(w.z, w.w);
            }
            b1r[oo] = __ldg(&fc1b[o]);
        }

#pragma unroll
        for (int pos = 0; pos < P; pos++) {
            uint64_t xp[8];
#pragma unroll
            for (int k = 0; k < 4; k++) {
                const float4 x = s_x[pos][lane + 32 * k];
                xp[2 * k]     = pack_f32x2(x.x, x.y);
                xp[2 * k + 1] = pack_f32x2(x.z, x.w);
            }
            float part[2];
#pragma unroll
            for (int oo = 0; oo < 2; oo++) {
                uint64_t acc = 0ull;
#pragma unroll
                for (int k = 0; k < 8; k++)
                    fma_f32x2(acc, wp[oo][k], xp[k]);
                const float2 f = unpack_f32x2(acc);
                part[oo] = f.x + f.y;
            }
#pragma unroll
            for (int off = 16; off > 0; off >>= 1) {
#pragma unroll
                for (int oo = 0; oo < 2; oo++)
                    part[oo] += __shfl_xor_sync(0xffffffffu, part[oo], off);
            }
            if (lane == 0) {
#pragma unroll
                for (int oo = 0; oo < 2; oo++)
                    s_h1[pos][4 * warp + 2 * ph + oo] =
                        fmaxf(part[oo] + b1r[oo], 0.f);
            }
        }
    }
    __syncthreads();

    // ---- FC2 (32->32, relu) + FC3 (32->1): warp w handles position w ----
    {
        const int pos = warp;
        const float* h = s_h1[pos];
        float s = __ldg(&fc2b[lane]);
        const float4* w2 = fc2w + (size_t)lane * 8;
#pragma unroll
        for (int k = 0; k < 8; k++) {
            const float4 w = __ldg(&w2[k]);
            s += w.x * h[4 * k + 0];
            s += w.y * h[4 * k + 1];
            s += w.z * h[4 * k + 2];
            s += w.w * h[4 * k + 3];
        }
        float v = fmaxf(s, 0.f) * __ldg(&fc3w[lane]);
#pragma unroll
        for (int off = 16; off > 0; off >>= 1)
            v += __shfl_xor_sync(0xffffffffu, v, off);
        if (lane == 0)
            out[p0 + pos] = v + __ldg(&fc3b[0]);
    }
}

extern "C" void kernel_launch(void* const* d_in, const int* in_sizes, int n_in,
                              void* d_out, int out_size)
{
    const int*    wiP   = (const int*)d_in[0];
    const int*    biP   = (const int*)d_in[2];
    const float4* ftw   = (const float4*)d_in[4];
    const float4* ftb   = (const float4*)d_in[5];
    const float4* fc1w  = (const float4*)d_in[6];
    const float*  fc1b  = (const float*)d_in[7];
    const float4* fc2w  = (const float4*)d_in[8];
    const float*  fc2b  = (const float*)d_in[9];
    const float*  fc3w  = (const float*)d_in[10];
    const float*  fc3b  = (const float*)d_in[11];
    float* outP = (float*)d_out;

    const int n_cvt = 2 * TBL_U4;
    cvt_kernel<<<(n_cvt + 255) / 256, 256>>>(ftw, ftb);
    nnue_kernel<<<GRID, NT>>>(wiP, biP, fc1w, fc1b,
                              fc2w, fc2b, fc3w, fc3b, outP);
}

// round 11
// speedup vs baseline: 1.0874x; 1.0874x over previous
#include <cuda_runtime.h>
#include <cuda_fp16.h>
#include <cstdint>

#define NUM_EMB 41025
#define BATCH   16384
#define BAG     30
#define P       8          // positions per block
#define NT      256
#define GRID    (BATCH / P)

#define ROW_U4  32                     // 256 halves = 32 uint4 per row
#define TBL_U4  (NUM_EMB * ROW_U4)     // 1,312,800 uint4 per table

// fp16 shadow tables (scratch): [0]=white, [1]=black. 21 MB each.
__device__ uint4 g_ft16[2][TBL_U4];

// ---- packed f32x2 helpers (Blackwell sm_103a) ----
__device__ __forceinline__ void add_f32x2(uint64_t& acc, uint64_t v) {
    asm("add.rn.f32x2 %0, %1, %2;" : "=l"(acc) : "l"(acc), "l"(v));
}
__device__ __forceinline__ void fma_f32x2(uint64_t& acc, uint64_t a, uint64_t b) {
    asm("fma.rn.f32x2 %0, %1, %2, %3;" : "=l"(acc) : "l"(a), "l"(b), "l"(acc));
}
__device__ __forceinline__ uint64_t h2_to_f32x2(__half2 h) {
    float2 f = __half22float2(h);
    uint64_t r;
    asm("mov.b64 %0, {%1, %2};" : "=l"(r) : "f"(f.x), "f"(f.y));
    return r;
}
__device__ __forceinline__ float2 unpack_f32x2(uint64_t v) {
    float2 f;
    asm("mov.b64 {%0, %1}, %2;" : "=f"(f.x), "=f"(f.y) : "l"(v));
    return f;
}
__device__ __forceinline__ uint64_t pack_f32x2(float x, float y) {
    uint64_t r;
    asm("mov.b64 %0, {%1, %2};" : "=l"(r) : "f"(x), "f"(y));
    return r;
}

// ---------------------------------------------------------------------------
// Pre-pass: convert both f32 tables to fp16.
// Streaming reads (__ldcs), L2-resident writes (__stcg).
// ---------------------------------------------------------------------------
__global__ __launch_bounds__(256)
void cvt_kernel(const float4* __restrict__ ftw, const float4* __restrict__ ftb)
{
    const int i = blockIdx.x * blockDim.x + threadIdx.x;
    if (i >= 2 * TBL_U4) return;
    const int tbl = (i >= TBL_U4);
    const int j   = tbl ? (i - TBL_U4) : i;
    const float4* src = tbl ? ftb : ftw;

    const float4 a = __ldcs(&src[2 * j]);
    const float4 b = __ldcs(&src[2 * j + 1]);

    __half2 h0 = __floats2half2_rn(a.x, a.y);
    __half2 h1 = __floats2half2_rn(a.z, a.w);
    __half2 h2 = __floats2half2_rn(b.x, b.y);
    __half2 h3 = __floats2half2_rn(b.z, b.w);

    uint4 o;
    o.x = *reinterpret_cast<unsigned*>(&h0);
    o.y = *reinterpret_cast<unsigned*>(&h1);
    o.z = *reinterpret_cast<unsigned*>(&h2);
    o.w = *reinterpret_cast<unsigned*>(&h3);
    __stcg(&g_ft16[tbl][j], o);
}

// ---------------------------------------------------------------------------
// Main kernel.
// ---------------------------------------------------------------------------
__global__ __launch_bounds__(NT, 3)
void nnue_kernel(const int* __restrict__ wi,
                 const int* __restrict__ bi,
                 const float4* __restrict__ fc1w,   // [32][128] float4
                 const float* __restrict__ fc1b,
                 const float4* __restrict__ fc2w,   // [32][8] float4
                 const float* __restrict__ fc2b,
                 const float* __restrict__ fc3w,
                 const float* __restrict__ fc3b,
                 float* __restrict__ out)
{
    __shared__ int    s_idx[P][2][BAG];
    __shared__ float4 s_x[P][128];     // concat(white,black) after relu
    __shared__ float  s_h1[P][32];

    const int tid  = threadIdx.x;
    const int lane = tid & 31;
    const int warp = tid >> 5;
    const int p0   = blockIdx.x * P;

    // ---- stage indices ----
    for (int i = tid; i < P * 2 * BAG; i += NT) {
        const int pp  = i / (2 * BAG);
        const int r   = i % (2 * BAG);
        const int tbl = r / BAG;
        const int j   = r % BAG;
        s_idx[pp][tbl][j] = tbl ? bi[(p0 + pp) * BAG + j]
                                : wi[(p0 + pp) * BAG + j];
    }
    __syncthreads();

    // ---- gather: warp w owns position w. fp16 rows via L1-bypassing __ldcg,
    //      chunk-of-3 HADD2 accumulation, merged into packed f32x2. ----
    {
        uint64_t accW[4], accB[4];         // f32x2 accumulators (8 cols)
#pragma unroll
        for (int k = 0; k < 4; k++) { accW[k] = 0ull; accB[k] = 0ull; }

        const uint4* tw = g_ft16[0];
        const uint4* tb = g_ft16[1];
        const int* iw_p = s_idx[warp][0];
        const int* ib_p = s_idx[warp][1];

#pragma unroll 2
        for (int c = 0; c < 10; c++) {     // 10 chunks x 3 rows
            __half2 hsW[4], hsB[4];
            {
                const int iw = iw_p[3 * c];
                const int ib = ib_p[3 * c];
                const uint4 vw = __ldcg(&tw[(size_t)iw * ROW_U4 + lane]);
                const uint4 vb = __ldcg(&tb[(size_t)ib * ROW_U4 + lane]);
                const __half2* hw = reinterpret_cast<const __half2*>(&vw);
                const __half2* hb = reinterpret_cast<const __half2*>(&vb);
#pragma unroll
                for (int k = 0; k < 4; k++) { hsW[k] = hw[k]; hsB[k] = hb[k]; }
            }
#pragma unroll
            for (int jj = 1; jj < 3; jj++) {
                const int iw = iw_p[3 * c + jj];
                const int ib = ib_p[3 * c + jj];
                const uint4 vw = __ldcg(&tw[(size_t)iw * ROW_U4 + lane]);
                const uint4 vb = __ldcg(&tb[(size_t)ib * ROW_U4 + lane]);
                const __half2* hw = reinterpret_cast<const __half2*>(&vw);
                const __half2* hb = reinterpret_cast<const __half2*>(&vb);
#pragma unroll
                for (int k = 0; k < 4; k++) {
                    hsW[k] = __hadd2(hsW[k], hw[k]);
                    hsB[k] = __hadd2(hsB[k], hb[k]);
                }
            }
#pragma unroll
            for (int k = 0; k < 4; k++) {
                add_f32x2(accW[k], h2_to_f32x2(hsW[k]));
                add_f32x2(accB[k], h2_to_f32x2(hsB[k]));
            }
        }

        // relu + store to smem. lane holds cols 8*lane..8*lane+7.
        float aw[8], ab[8];
#pragma unroll
        for (int k = 0; k < 4; k++) {
            const float2 fw = unpack_f32x2(accW[k]);
            const float2 fb = unpack_f32x2(accB[k]);
            aw[2 * k]     = fmaxf(fw.x, 0.f);
            aw[2 * k + 1] = fmaxf(fw.y, 0.f);
            ab[2 * k]     = fmaxf(fb.x, 0.f);
            ab[2 * k + 1] = fmaxf(fb.y, 0.f);
        }
        s_x[warp][2 * lane]          = make_float4(aw[0], aw[1], aw[2], aw[3]);
        s_x[warp][2 * lane + 1]      = make_float4(aw[4], aw[5], aw[6], aw[7]);
        s_x[warp][64 + 2 * lane]     = make_float4(ab[0], ab[1], ab[2], ab[3]);
        s_x[warp][64 + 2 * lane + 1] = make_float4(ab[4], ab[5], ab[6], ab[7]);
    }
    __syncthreads();

    // ---- FC1 in 2 phases: warp computes outputs 4*warp+2*ph+{0,1} for all
    //      8 positions. Only 16 weight f32x2 regs live at a time. ----
#pragma unroll
    for (int ph = 0; ph < 2; ph++) {
        uint64_t wp[2][8];
        float    b1r[2];
#pragma unroll
        for (int oo = 0; oo < 2; oo++) {
            const int o = 4 * warp + 2 * ph + oo;
#pragma unroll
            for (int k = 0; k < 4; k++) {
                const float4 w = __ldg(&fc1w[(size_t)o * 128 + lane + 32 * k]);
                wp[oo][2 * k]     = pack_f32x2(w.x, w.y);
                wp[oo][2 * k + 1] = pack_f32x2(w.z, w.w);
            }
            b1r[oo] = __ldg(&fc1b[o]);
        }

#pragma unroll
        for (int pos = 0; pos < P; pos++) {
            uint64_t xp[8];
#pragma unroll
            for (int k = 0; k < 4; k++) {
                const float4 x = s_x[pos][lane + 32 * k];
                xp[2 * k]     = pack_f32x2(x.x, x.y);
                xp[2 * k + 1] = pack_f32x2(x.z, x.w);
            }
            float part[2];
#pragma unroll
            for (int oo = 0; oo < 2; oo++) {
                uint64_t acc = 0ull;
#pragma unroll
                for (int k = 0; k < 8; k++)
                    fma_f32x2(acc, wp[oo][k], xp[k]);
                const float2 f = unpack_f32x2(acc);
                part[oo] = f.x + f.y;
            }
#pragma unroll
            for (int off = 16; off > 0; off >>= 1) {
#pragma unroll
                for (int oo = 0; oo < 2; oo++)
                    part[oo] += __shfl_xor_sync(0xffffffffu, part[oo], off);
            }
            if (lane == 0) {
#pragma unroll
                for (int oo = 0; oo < 2; oo++)
                    s_h1[pos][4 * warp + 2 * ph + oo] =
                        fmaxf(part[oo] + b1r[oo], 0.f);
            }
        }
    }
    __syncthreads();

    // ---- FC2 (32->32, relu) + FC3 (32->1): warp w handles position w ----
    {
        const int pos = warp;
        const float* h = s_h1[pos];
        float s = __ldg(&fc2b[lane]);
        const float4* w2 = fc2w + (size_t)lane * 8;
#pragma unroll
        for (int k = 0; k < 8; k++) {
            const float4 w = __ldg(&w2[k]);
            s += w.x * h[4 * k + 0];
            s += w.y * h[4 * k + 1];
            s += w.z * h[4 * k + 2];
            s += w.w * h[4 * k + 3];
        }
        float v = fmaxf(s, 0.f) * __ldg(&fc3w[lane]);
#pragma unroll
        for (int off = 16; off > 0; off >>= 1)
            v += __shfl_xor_sync(0xffffffffu, v, off);
        if (lane == 0)
            out[p0 + pos] = v + __ldg(&fc3b[0]);
    }
}

extern "C" void kernel_launch(void* const* d_in, const int* in_sizes, int n_in,
                              void* d_out, int out_size)
{
    const int*    wiP   = (const int*)d_in[0];
    const int*    biP   = (const int*)d_in[2];
    const float4* ftw   = (const float4*)d_in[4];
    const float4* ftb   = (const float4*)d_in[5];
    const float4* fc1w  = (const float4*)d_in[6];
    const float*  fc1b  = (const float*)d_in[7];
    const float4* fc2w  = (const float4*)d_in[8];
    const float*  fc2b  = (const float*)d_in[9];
    const float*  fc3w  = (const float*)d_in[10];
    const float*  fc3b  = (const float*)d_in[11];
    float* outP = (float*)d_out;

    const int n_cvt = 2 * TBL_U4;
    cvt_kernel<<<(n_cvt + 255) / 256, 256>>>(ftw, ftb);
    nnue_kernel<<<GRID, NT>>>(wiP, biP, fc1w, fc1b,
                              fc2w, fc2b, fc3w, fc3b, outP);
}

// round 12
// speedup vs baseline: 1.1653x; 1.0716x over previous
#include <cuda_runtime.h>
#include <cuda_fp16.h>
#include <cstdint>

#define NUM_EMB 41025
#define BATCH   16384
#define BAG     30
#define BAGP    32         // padded bag (pad index = 0 -> zero row)
#define P       8          // positions per block
#define NT      256
#define GRID    (BATCH / P)

#define ROW_U4  32                     // 256 halves = 32 uint4 per row
#define TBL_U4  (NUM_EMB * ROW_U4)     // 1,312,800 uint4 per table

// fp16 shadow tables (scratch): [0]=white, [1]=black. 21 MB each.
__device__ uint4 g_ft16[2][TBL_U4];

// ---- packed f32x2 helpers (Blackwell sm_103a) ----
__device__ __forceinline__ void add_f32x2(uint64_t& acc, uint64_t v) {
    asm("add.rn.f32x2 %0, %1, %2;" : "=l"(acc) : "l"(acc), "l"(v));
}
__device__ __forceinline__ void fma_f32x2(uint64_t& acc, uint64_t a, uint64_t b) {
    asm("fma.rn.f32x2 %0, %1, %2, %3;" : "=l"(acc) : "l"(a), "l"(b), "l"(acc));
}
__device__ __forceinline__ uint64_t h2_to_f32x2(__half2 h) {
    float2 f = __half22float2(h);
    uint64_t r;
    asm("mov.b64 %0, {%1, %2};" : "=l"(r) : "f"(f.x), "f"(f.y));
    return r;
}
__device__ __forceinline__ float2 unpack_f32x2(uint64_t v) {
    float2 f;
    asm("mov.b64 {%0, %1}, %2;" : "=f"(f.x), "=f"(f.y) : "l"(v));
    return f;
}
__device__ __forceinline__ uint64_t pack_f32x2(float x, float y) {
    uint64_t r;
    asm("mov.b64 %0, {%1, %2};" : "=l"(r) : "f"(x), "f"(y));
    return r;
}

// ---------------------------------------------------------------------------
// Pre-pass: convert both f32 tables to fp16 (streaming reads, L2 writes).
// ---------------------------------------------------------------------------
__global__ __launch_bounds__(256)
void cvt_kernel(const float4* __restrict__ ftw, const float4* __restrict__ ftb)
{
    const int i = blockIdx.x * blockDim.x + threadIdx.x;
    if (i >= 2 * TBL_U4) return;
    const int tbl = (i >= TBL_U4);
    const int j   = tbl ? (i - TBL_U4) : i;
    const float4* src = tbl ? ftb : ftw;

    const float4 a = __ldcs(&src[2 * j]);
    const float4 b = __ldcs(&src[2 * j + 1]);

    __half2 h0 = __floats2half2_rn(a.x, a.y);
    __half2 h1 = __floats2half2_rn(a.z, a.w);
    __half2 h2 = __floats2half2_rn(b.x, b.y);
    __half2 h3 = __floats2half2_rn(b.z, b.w);

    uint4 o;
    o.x = *reinterpret_cast<unsigned*>(&h0);
    o.y = *reinterpret_cast<unsigned*>(&h1);
    o.z = *reinterpret_cast<unsigned*>(&h2);
    o.w = *reinterpret_cast<unsigned*>(&h3);
    __stcg(&g_ft16[tbl][j], o);
}

// ---------------------------------------------------------------------------
// Main kernel.
// ---------------------------------------------------------------------------
__global__ __launch_bounds__(NT, 2)
void nnue_kernel(const int* __restrict__ wi,
                 const int* __restrict__ bi,
                 const float4* __restrict__ fc1w,   // [32][128] float4
                 const float* __restrict__ fc1b,
                 const float4* __restrict__ fc2w,   // [32][8] float4
                 const float* __restrict__ fc2b,
                 const float* __restrict__ fc3w,
                 const float* __restrict__ fc3b,
                 float* __restrict__ out)
{
    __shared__ __align__(16) int     s_idx[P][2][BAGP];
    __shared__ __align__(16) __half2 s_xh[P][256];   // concat x, fp16
    __shared__ float s_h1[P][32];

    const int tid  = threadIdx.x;
    const int lane = tid & 31;
    const int warp = tid >> 5;
    const int p0   = blockIdx.x * P;

    // ---- stage indices (padded to 32; pad index 0 -> all-zero table row) ----
    for (int i = tid; i < P * 2 * BAGP; i += NT) {
        const int pp  = i / (2 * BAGP);
        const int r   = i % (2 * BAGP);
        const int tbl = r / BAGP;
        const int j   = r % BAGP;
        int v = 0;
        if (j < BAG)
            v = tbl ? bi[(p0 + pp) * BAG + j] : wi[(p0 + pp) * BAG + j];
        s_idx[pp][tbl][j] = v;
    }
    __syncthreads();

    // ---- gather: warp w owns position w. 8 chunks x 4 rows per table.
    //      int4 index loads, HADD2 partial sums, f32x2 accumulate. ----
    {
        uint64_t accW[4], accB[4];
#pragma unroll
        for (int k = 0; k < 4; k++) { accW[k] = 0ull; accB[k] = 0ull; }

        const uint4* tw = g_ft16[0];
        const uint4* tb = g_ft16[1];
        const int4* iw4 = reinterpret_cast<const int4*>(s_idx[warp][0]);
        const int4* ib4 = reinterpret_cast<const int4*>(s_idx[warp][1]);

#pragma unroll
        for (int c = 0; c < 8; c++) {      // 8 chunks x 4 rows
            const int4 iw = iw4[c];
            const int4 ib = ib4[c];

            uint4 vw0 = __ldcg(&tw[(size_t)iw.x * ROW_U4 + lane]);
            uint4 vw1 = __ldcg(&tw[(size_t)iw.y * ROW_U4 + lane]);
            uint4 vw2 = __ldcg(&tw[(size_t)iw.z * ROW_U4 + lane]);
            uint4 vw3 = __ldcg(&tw[(size_t)iw.w * ROW_U4 + lane]);
            uint4 vb0 = __ldcg(&tb[(size_t)ib.x * ROW_U4 + lane]);
            uint4 vb1 = __ldcg(&tb[(size_t)ib.y * ROW_U4 + lane]);
            uint4 vb2 = __ldcg(&tb[(size_t)ib.z * ROW_U4 + lane]);
            uint4 vb3 = __ldcg(&tb[(size_t)ib.w * ROW_U4 + lane]);

            const __half2* w0 = reinterpret_cast<const __half2*>(&vw0);
            const __half2* w1 = reinterpret_cast<const __half2*>(&vw1);
            const __half2* w2 = reinterpret_cast<const __half2*>(&vw2);
            const __half2* w3 = reinterpret_cast<const __half2*>(&vw3);
            const __half2* b0 = reinterpret_cast<const __half2*>(&vb0);
            const __half2* b1 = reinterpret_cast<const __half2*>(&vb1);
            const __half2* b2 = reinterpret_cast<const __half2*>(&vb2);
            const __half2* b3 = reinterpret_cast<const __half2*>(&vb3);

#pragma unroll
            for (int k = 0; k < 4; k++) {
                __half2 hw = __hadd2(__hadd2(w0[k], w1[k]),
                                     __hadd2(w2[k], w3[k]));
                __half2 hb = __hadd2(__hadd2(b0[k], b1[k]),
                                     __hadd2(b2[k], b3[k]));
                add_f32x2(accW[k], h2_to_f32x2(hw));
                add_f32x2(accB[k], h2_to_f32x2(hb));
            }
        }

        // relu in f32, convert to fp16, store: 2 x STS.128 per warp.
        __half2 hW[4], hB[4];
#pragma unroll
        for (int k = 0; k < 4; k++) {
            float2 fw = unpack_f32x2(accW[k]);
            float2 fb = unpack_f32x2(accB[k]);
            hW[k] = __floats2half2_rn(fmaxf(fw.x, 0.f), fmaxf(fw.y, 0.f));
            hB[k] = __floats2half2_rn(fmaxf(fb.x, 0.f), fmaxf(fb.y, 0.f));
        }
        *reinterpret_cast<uint4*>(&s_xh[warp][4 * lane]) =
            *reinterpret_cast<uint4*>(hW);          // white cols 8l..8l+7
        *reinterpret_cast<uint4*>(&s_xh[warp][128 + 4 * lane]) =
            *reinterpret_cast<uint4*>(hB);          // black cols 256+8l..
    }

    // ---- FC1 weights -> 64 registers (once per block) ----
    uint64_t wp[4][8];
    float    b1r[4];
#pragma unroll
    for (int oo = 0; oo < 4; oo++) {
        const int o = 4 * warp + oo;
#pragma unroll
        for (int k = 0; k < 4; k++) {
            const float4 w = __ldg(&fc1w[(size_t)o * 128 + lane + 32 * k]);
            wp[oo][2 * k]     = pack_f32x2(w.x, w.y);
            wp[oo][2 * k + 1] = pack_f32x2(w.z, w.w);
        }
        b1r[oo] = __ldg(&fc1b[o]);
    }
    __syncthreads();

    // ---- FC1: warp computes its 4 outputs for all 8 positions.
    //      x read as fp16 (4 x LDS.64 per position). ----
#pragma unroll
    for (int pos = 0; pos < P; pos++) {
        uint64_t xp[8];
#pragma unroll
        for (int k = 0; k < 4; k++) {
            const uint2 v = *reinterpret_cast<const uint2*>(
                &s_xh[pos][2 * (lane + 32 * k)]);
            const __half2 lo = *reinterpret_cast<const __half2*>(&v.x);
            const __half2 hi = *reinterpret_cast<const __half2*>(&v.y);
            xp[2 * k]     = h2_to_f32x2(lo);
            xp[2 * k + 1] = h2_to_f32x2(hi);
        }
        float part[4];
#pragma unroll
        for (int oo = 0; oo < 4; oo++) {
            uint64_t acc = 0ull;
#pragma unroll
            for (int k = 0; k < 8; k++)
                fma_f32x2(acc, wp[oo][k], xp[k]);
            const float2 f = unpack_f32x2(acc);
            part[oo] = f.x + f.y;
        }
#pragma unroll
        for (int off = 16; off > 0; off >>= 1) {
#pragma unroll
            for (int oo = 0; oo < 4; oo++)
                part[oo] += __shfl_xor_sync(0xffffffffu, part[oo], off);
        }
        if (lane == 0) {
#pragma unroll
            for (int oo = 0; oo < 4; oo++)
                s_h1[pos][4 * warp + oo] = fmaxf(part[oo] + b1r[oo], 0.f);
        }
    }
    __syncthreads();

    // ---- FC2 (32->32, relu) + FC3 (32->1): warp w handles position w ----
    {
        const int pos = warp;
        const float* h = s_h1[pos];
        float s = __ldg(&fc2b[lane]);
        const float4* w2 = fc2w + (size_t)lane * 8;
#pragma unroll
        for (int k = 0; k < 8; k++) {
            const float4 w = __ldg(&w2[k]);
            s += w.x * h[4 * k + 0];
            s += w.y * h[4 * k + 1];
            s += w.z * h[4 * k + 2];
            s += w.w * h[4 * k + 3];
        }
        float v = fmaxf(s, 0.f) * __ldg(&fc3w[lane]);
#pragma unroll
        for (int off = 16; off > 0; off >>= 1)
            v += __shfl_xor_sync(0xffffffffu, v, off);
        if (lane == 0)
            out[p0 + pos] = v + __ldg(&fc3b[0]);
    }
}

extern "C" void kernel_launch(void* const* d_in, const int* in_sizes, int n_in,
                              void* d_out, int out_size)
{
    const int*    wiP   = (const int*)d_in[0];
    const int*    biP   = (const int*)d_in[2];
    const float4* ftw   = (const float4*)d_in[4];
    const float4* ftb   = (const float4*)d_in[5];
    const float4* fc1w  = (const float4*)d_in[6];
    const float*  fc1b  = (const float*)d_in[7];
    const float4* fc2w  = (const float4*)d_in[8];
    const float*  fc2b  = (const float*)d_in[9];
    const float*  fc3w  = (const float*)d_in[10];
    const float*  fc3b  = (const float*)d_in[11];
    float* outP = (float*)d_out;

    const int n_cvt = 2 * TBL_U4;
    cvt_kernel<<<(n_cvt + 255) / 256, 256>>>(ftw, ftb);
    nnue_kernel<<<GRID, NT>>>(wiP, biP, fc1w, fc1b,
                              fc2w, fc2b, fc3w, fc3b, outP);
}